// round 8
// baseline (speedup 1.0000x reference)
#include <cuda_runtime.h>
#include <cuda_bf16.h>
#include <cstdint>

#define BATCH 256
#define NA 196
#define NB 196
#define DK 256
#define DIM 1024
#define SMOOTH_F 4.0f
#define NP 224   // padded n / a dims

// Pre-split attention planes: attnT[b][n][a], bf16 high & low parts, zero-padded.
__device__ unsigned short g_ah[(size_t)BATCH * NP * NP];
__device__ unsigned short g_al[(size_t)BATCH * NP * NP];

typedef unsigned int u32;

__device__ __forceinline__ u32 smem_u32(const void* p) {
    u32 a;
    asm("{ .reg .u64 t; cvta.to.shared.u64 t, %1; cvt.u32.u64 %0, t; }" : "=r"(a) : "l"(p));
    return a;
}
__device__ __forceinline__ void split2(float x, unsigned short& h, unsigned short& l) {
    __nv_bfloat16 hb = __float2bfloat16_rn(x);
    float r = x - __bfloat162float(hb);
    h = __bfloat16_as_ushort(hb);
    l = __bfloat16_as_ushort(__float2bfloat16_rn(r));
}

#define LDMX4(r, a) asm volatile( \
    "ldmatrix.sync.aligned.m8n8.x4.shared.b16 {%0,%1,%2,%3}, [%4];" \
    : "=r"((r)[0]), "=r"((r)[1]), "=r"((r)[2]), "=r"((r)[3]) : "r"(a))

#define MMA16816(d, a, b0, b1) asm volatile( \
    "mma.sync.aligned.m16n8k16.row.col.f32.bf16.bf16.f32 " \
    "{%0,%1,%2,%3}, {%4,%5,%6,%7}, {%8,%9}, {%0,%1,%2,%3};" \
    : "+f"((d)[0]), "+f"((d)[1]), "+f"((d)[2]), "+f"((d)[3]) \
    : "r"((a)[0]), "r"((a)[1]), "r"((a)[2]), "r"((a)[3]), "r"(b0), "r"(b1))

#define CPASYNC16(dst, src) asm volatile( \
    "cp.async.cg.shared.global [%0], [%1], 16;" :: "r"(dst), "l"(src))
#define CPCOMMIT() asm volatile("cp.async.commit_group;")
#define CPWAIT1() asm volatile("cp.async.wait_group 1;")

// ============================================================================
// K1: energyT[n][a] = K_b^T @ Q_a^T (2-term split, 3 MMA products),
//     warp-parallel column softmax, write pre-split attn planes.
// Block: (a-half, batch). 448 threads = 14 warps; warp = 16 n-rows x 112 a-cols.
// ============================================================================
#define K1_AH 0u
#define K1_AL 17920u      // A planes: [224 n][32 k] bf16, 80B row stride
#define K1_BH 35840u      // B planes: [112 a][32 k] bf16, 80B row stride
#define K1_BL 44800u      // staging end = 53760; Csm overlay [224][116] f32
#define K1_SINV 103936u   // 112 floats
#define K1_SMEM 104384u

__global__ void __launch_bounds__(448) xattn_k1(
    const float* __restrict__ Q,    // [B, NA, DK]
    const float* __restrict__ Kb)   // [B, DK, NB]
{
    extern __shared__ char smp[];
    const u32 sb = smem_u32(smp);
    const int t = threadIdx.x, lane = t & 31, w = t >> 5;
    const int a0 = blockIdx.x * 112;
    const int b  = blockIdx.y;

    const float* qb = Q + (size_t)b * NA * DK;
    const float* kb = Kb + (size_t)b * DK * NB;

    float acc[14][4];
    #pragma unroll
    for (int j = 0; j < 14; j++)
        #pragma unroll
        for (int q = 0; q < 4; q++) acc[j][q] = 0.f;

    const int ga = t / 224;          // k-half for A fill
    const int tn = t - ga * 224;     // n row for A fill

    #pragma unroll 1
    for (int kc = 0; kc < 8; kc++) {
        __syncthreads();
        // A = K^T: row n = tn, cols kk (16 per half-group). Coalesced along n.
        #pragma unroll
        for (int i = 0; i < 16; i++) {
            int kk = ga * 16 + i;
            float v = (tn < NB) ? kb[(size_t)(kc * 32 + kk) * NB + tn] : 0.f;
            unsigned short h, l;
            split2(v, h, l);
            *(unsigned short*)(smp + K1_AH + tn * 80 + kk * 2) = h;
            *(unsigned short*)(smp + K1_AL + tn * 80 + kk * 2) = l;
        }
        // B = Q rows (a-local 112) x 32 k
        #pragma unroll
        for (int i = 0; i < 8; i++) {
            int idx = t + i * 448;
            int r = idx >> 5, kk = idx & 31;
            int a = a0 + r;
            float v = (a < NA) ? qb[(size_t)a * DK + kc * 32 + kk] : 0.f;
            unsigned short h, l;
            split2(v, h, l);
            *(unsigned short*)(smp + K1_BH + r * 80 + kk * 2) = h;
            *(unsigned short*)(smp + K1_BL + r * 80 + kk * 2) = l;
        }
        __syncthreads();

        #pragma unroll
        for (int ks = 0; ks < 2; ks++) {
            u32 ah[4], al[4];
            {
                u32 arow = w * 16 + (lane & 15);
                u32 acol = ks * 32 + ((lane >> 4) << 4);
                LDMX4(ah, sb + K1_AH + arow * 80 + acol);
                LDMX4(al, sb + K1_AL + arow * 80 + acol);
            }
            #pragma unroll
            for (int jj = 0; jj < 7; jj++) {
                u32 brow = jj * 16 + ((lane >> 4) << 3) + (lane & 7);
                u32 bcol = ks * 32 + (((lane >> 3) & 1) << 4);
                u32 bh[4], bl[4];
                LDMX4(bh, sb + K1_BH + brow * 80 + bcol);
                LDMX4(bl, sb + K1_BL + brow * 80 + bcol);
                #pragma unroll
                for (int hf = 0; hf < 2; hf++) {
                    int j = jj * 2 + hf;
                    MMA16816(acc[j], ah, bh[hf * 2], bh[hf * 2 + 1]);
                    MMA16816(acc[j], ah, bl[hf * 2], bl[hf * 2 + 1]);
                    MMA16816(acc[j], al, bh[hf * 2], bh[hf * 2 + 1]);
                }
            }
        }
    }
    __syncthreads();   // staging dead; reuse as Csm [224 n][116 f32]

    float* Csm = (float*)smp;
    float* sinv = (float*)(smp + K1_SINV);
    const int g = lane >> 2, tq = lane & 3;
    #pragma unroll
    for (int j = 0; j < 14; j++) {
        int row = w * 16 + g;
        int col = j * 8 + tq * 2;
        *(float2*)&Csm[row * 116 + col] = make_float2(acc[j][0], acc[j][1]);
        *(float2*)&Csm[(row + 8) * 116 + col] = make_float2(acc[j][2], acc[j][3]);
    }
    __syncthreads();

    // Warp-parallel column softmax: warp w -> a-cols [w*8, w*8+8).
    #pragma unroll 1
    for (int ci = 0; ci < 8; ci++) {
        int c = w * 8 + ci;
        float M = -1e30f;
        #pragma unroll
        for (int r = 0; r < 7; r++) {
            int n = lane + r * 32;
            if (n < NB) M = fmaxf(M, Csm[n * 116 + c]);
        }
        #pragma unroll
        for (int o = 16; o; o >>= 1)
            M = fmaxf(M, __shfl_xor_sync(0xFFFFFFFFu, M, o));
        float S = 0.f;
        #pragma unroll
        for (int r = 0; r < 7; r++) {
            int n = lane + r * 32;
            if (n < NB) {
                float e = __expf(SMOOTH_F * (Csm[n * 116 + c] - M));
                Csm[n * 116 + c] = e;
                S += e;
            }
        }
        #pragma unroll
        for (int o = 16; o; o >>= 1)
            S += __shfl_xor_sync(0xFFFFFFFFu, S, o);
        if (lane == 0)
            sinv[c] = (a0 + c < NA) ? (1.f / S) : 0.f;
    }
    __syncthreads();

    // Write pre-split planes (coalesced rows; zero rows for n >= 196).
    if (lane < 28) {
        float4 s4 = *(float4*)&sinv[lane * 4];
        for (int r = w; r < NP; r += 14) {
            uint2 hh = make_uint2(0u, 0u), ll = make_uint2(0u, 0u);
            if (r < NB) {
                float4 p = *(float4*)&Csm[r * 116 + lane * 4];
                p.x *= s4.x; p.y *= s4.y; p.z *= s4.z; p.w *= s4.w;
                unsigned short h[4], l[4];
                split2(p.x, h[0], l[0]); split2(p.y, h[1], l[1]);
                split2(p.z, h[2], l[2]); split2(p.w, h[3], l[3]);
                hh = make_uint2((u32)h[0] | ((u32)h[1] << 16), (u32)h[2] | ((u32)h[3] << 16));
                ll = make_uint2((u32)l[0] | ((u32)l[1] << 16), (u32)l[2] | ((u32)l[3] << 16));
            }
            size_t off = (size_t)(b * NP + r) * NP + a0 + lane * 4;
            *(uint2*)(g_ah + off) = hh;
            *(uint2*)(g_al + off) = ll;
        }
    }
}

// ============================================================================
// K2: out = gamma + V_a @ attn + V_b.
// Block: (m-tile 128 dims, batch). 512 threads = 16 warps (8 M x 2 N),
// warp tile m16 x n112. A (V_a split) resident full-K; B cp.async double-buf.
// ============================================================================
#define K2_AH 0u
#define K2_AL 59392u                  // A planes: [128][224 k] bf16, 464B stride
#define K2_B0 118784u                 // B stages: [224 n][32 k] bf16, 80B stride
#define K2_BSTAGE 35840u              // per stage: 2 planes x 17920
#define K2_SMEM 190464u

__global__ void __launch_bounds__(512) xattn_k2(
    const float* __restrict__ VA,   // [B, DIM, NA]
    const float* __restrict__ VB,   // [B, DIM, NB]
    const float* __restrict__ G,
    float* __restrict__ O)          // [B, DIM, NB]
{
    extern __shared__ char smp[];
    const u32 sb = smem_u32(smp);
    const int t = threadIdx.x, lane = t & 31, w = t >> 5;
    const int wm = w >> 1, wn = w & 1;
    const int m0 = blockIdx.x * 128;
    const int b  = blockIdx.y;

    const float* va = VA + ((size_t)b * DIM + m0) * NA;
    const char* ghp = (const char*)g_ah;
    const char* glp = (const char*)g_al;

    // prefetch B chunk 0 into stage 0
    {
        #pragma unroll
        for (int i = 0; i < 4; i++) {
            int idx = t + i * 512;
            if (idx < 1792) {
                int p = idx / 896, rem = idx % 896;
                int n = rem >> 2, c = rem & 3;
                u32 dst = sb + K2_B0 + p * 17920 + n * 80 + c * 16;
                const char* base = p ? glp : ghp;
                const char* src = base + ((size_t)(b * NP + n) * NP + c * 8) * 2;
                CPASYNC16(dst, src);
            }
        }
        CPCOMMIT();
    }

    // Fill resident A planes: V_a split, rows m (128) x k=a (224, zero-pad)
    #pragma unroll
    for (int i = 0; i < 14; i++) {
        int idx = t + i * 512;
        int row = idx / 56, q4 = idx % 56;
        int col = q4 * 4;
        float4 v = make_float4(0.f, 0.f, 0.f, 0.f);
        if (col < NA) v = *(const float4*)(va + (size_t)row * NA + col);
        unsigned short h[4], l[4];
        split2(v.x, h[0], l[0]); split2(v.y, h[1], l[1]);
        split2(v.z, h[2], l[2]); split2(v.w, h[3], l[3]);
        *(uint2*)(smp + K2_AH + row * 464 + col * 2) =
            make_uint2((u32)h[0] | ((u32)h[1] << 16), (u32)h[2] | ((u32)h[3] << 16));
        *(uint2*)(smp + K2_AL + row * 464 + col * 2) =
            make_uint2((u32)l[0] | ((u32)l[1] << 16), (u32)l[2] | ((u32)l[3] << 16));
    }

    float acc[14][4];
    #pragma unroll
    for (int j = 0; j < 14; j++)
        #pragma unroll
        for (int q = 0; q < 4; q++) acc[j][q] = 0.f;

    #pragma unroll 1
    for (int kc = 0; kc < 7; kc++) {
        if (kc < 6) {   // prefetch next chunk
            const int nk = kc + 1, st = nk & 1;
            #pragma unroll
            for (int i = 0; i < 4; i++) {
                int idx = t + i * 512;
                if (idx < 1792) {
                    int p = idx / 896, rem = idx % 896;
                    int n = rem >> 2, c = rem & 3;
                    u32 dst = sb + K2_B0 + st * K2_BSTAGE + p * 17920 + n * 80 + c * 16;
                    const char* base = p ? glp : ghp;
                    const char* src = base + ((size_t)(b * NP + n) * NP + nk * 32 + c * 8) * 2;
                    CPASYNC16(dst, src);
                }
            }
        }
        CPCOMMIT();
        CPWAIT1();
        __syncthreads();

        const u32 bhb = sb + K2_B0 + (kc & 1) * K2_BSTAGE;
        const u32 blb = bhb + 17920;

        #pragma unroll
        for (int ks = 0; ks < 2; ks++) {
            u32 ah[4], al[4];
            {
                u32 arow = wm * 16 + (lane & 15);
                u32 acol = (kc * 2 + ks) * 32 + ((lane >> 4) << 4);
                LDMX4(ah, sb + K2_AH + arow * 464 + acol);
                LDMX4(al, sb + K2_AL + arow * 464 + acol);
            }
            #pragma unroll
            for (int jj = 0; jj < 7; jj++) {
                u32 brow = wn * 112 + jj * 16 + ((lane >> 4) << 3) + (lane & 7);
                u32 bcol = ks * 32 + (((lane >> 3) & 1) << 4);
                u32 bh[4], bl[4];
                LDMX4(bh, bhb + brow * 80 + bcol);
                LDMX4(bl, blb + brow * 80 + bcol);
                #pragma unroll
                for (int hf = 0; hf < 2; hf++) {
                    int j = jj * 2 + hf;
                    MMA16816(acc[j], ah, bh[hf * 2], bh[hf * 2 + 1]);
                    MMA16816(acc[j], ah, bl[hf * 2], bl[hf * 2 + 1]);
                    MMA16816(acc[j], al, bh[hf * 2], bh[hf * 2 + 1]);
                }
            }
        }
        __syncthreads();
    }

    // Epilogue: out = gamma + acc + V_b (guarded float2 stores)
    const float gam = G[0];
    const int g = lane >> 2, tq = lane & 3;
    #pragma unroll
    for (int j = 0; j < 14; j++) {
        int n = wn * 112 + j * 8 + tq * 2;
        if (n < NB) {
            int row = m0 + wm * 16 + g;
            size_t o0 = ((size_t)(b * DIM + row)) * NB + n;
            size_t o1 = o0 + (size_t)8 * NB;
            float2 v0 = *(const float2*)(VB + o0);
            float2 v1 = *(const float2*)(VB + o1);
            *(float2*)(O + o0) = make_float2(gam + acc[j][0] + v0.x,
                                             gam + acc[j][1] + v0.y);
            *(float2*)(O + o1) = make_float2(gam + acc[j][2] + v1.x,
                                             gam + acc[j][3] + v1.y);
        }
    }
}

// ============================================================================
extern "C" void kernel_launch(void* const* d_in, const int* in_sizes, int n_in,
                              void* d_out, int out_size)
{
    const float* query_a = (const float*)d_in[0];
    const float* value_a = (const float*)d_in[1];
    const float* key_b   = (const float*)d_in[2];
    const float* value_b = (const float*)d_in[3];
    const float* gamma   = (const float*)d_in[4];
    float* out = (float*)d_out;

    cudaFuncSetAttribute(xattn_k1, cudaFuncAttributeMaxDynamicSharedMemorySize, K1_SMEM);
    cudaFuncSetAttribute(xattn_k2, cudaFuncAttributeMaxDynamicSharedMemorySize, K2_SMEM);

    xattn_k1<<<dim3(2, BATCH), 448, K1_SMEM>>>(query_a, key_b);
    xattn_k2<<<dim3(8, BATCH), 512, K2_SMEM>>>(value_a, value_b, gamma, out);
}

// round 9
// speedup vs baseline: 1.3660x; 1.3660x over previous
#include <cuda_runtime.h>
#include <cuda_bf16.h>
#include <cstdint>

#define BATCH 256
#define NA 196
#define NB 196
#define DK 256
#define DIM 1024
#define SMOOTH_F 4.0f
#define NP 224   // padded n / a dims

// Pre-split attention planes: attnT[b][n][a], bf16 high & low parts, zero-padded.
__device__ unsigned short g_ah[(size_t)BATCH * NP * NP];
__device__ unsigned short g_al[(size_t)BATCH * NP * NP];

typedef unsigned int u32;

__device__ __forceinline__ u32 smem_u32(const void* p) {
    u32 a;
    asm("{ .reg .u64 t; cvta.to.shared.u64 t, %1; cvt.u32.u64 %0, t; }" : "=r"(a) : "l"(p));
    return a;
}
__device__ __forceinline__ void split2(float x, unsigned short& h, unsigned short& l) {
    __nv_bfloat16 hb = __float2bfloat16_rn(x);
    float r = x - __bfloat162float(hb);
    h = __bfloat16_as_ushort(hb);
    l = __bfloat16_as_ushort(__float2bfloat16_rn(r));
}

#define LDMX4(r, a) asm volatile( \
    "ldmatrix.sync.aligned.m8n8.x4.shared.b16 {%0,%1,%2,%3}, [%4];" \
    : "=r"((r)[0]), "=r"((r)[1]), "=r"((r)[2]), "=r"((r)[3]) : "r"(a))

#define MMA16816(d, a, b0, b1) asm volatile( \
    "mma.sync.aligned.m16n8k16.row.col.f32.bf16.bf16.f32 " \
    "{%0,%1,%2,%3}, {%4,%5,%6,%7}, {%8,%9}, {%0,%1,%2,%3};" \
    : "+f"((d)[0]), "+f"((d)[1]), "+f"((d)[2]), "+f"((d)[3]) \
    : "r"((a)[0]), "r"((a)[1]), "r"((a)[2]), "r"((a)[3]), "r"(b0), "r"(b1))

#define CPASYNC16(dst, src) asm volatile( \
    "cp.async.cg.shared.global [%0], [%1], 16;" :: "r"(dst), "l"(src))
#define CPCOMMIT() asm volatile("cp.async.commit_group;")
#define CPWAIT1() asm volatile("cp.async.wait_group 1;")

// ============================================================================
// K1: energyT[n][a] = K_b^T @ Q_a^T (2-term split, 3 MMA products),
//     warp-parallel column softmax, write pre-split attn planes.
// Block: (a-half, batch). 224 threads = 7 warps; warp = 32 n-rows x 112 a-cols.
// (Round-7 MMA structure: m32 warp tiles — do NOT thin the warp tile; that
//  doubles LDSM traffic and regressed in round 8.)
// ============================================================================
#define K1_AH 0u
#define K1_AL 17920u      // A planes: [224 n][32 k] bf16, 80B row stride
#define K1_BH 35840u      // B planes: [112 a][32 k] bf16, 80B row stride
#define K1_BL 44800u      // staging end = 53760; Csm overlay [224][116] f32
#define K1_SINV 103936u   // 112 floats
#define K1_SMEM 104384u

__global__ void __launch_bounds__(224) xattn_k1(
    const float* __restrict__ Q,    // [B, NA, DK]
    const float* __restrict__ Kb)   // [B, DK, NB]
{
    extern __shared__ char smp[];
    const u32 sb = smem_u32(smp);
    const int t = threadIdx.x, lane = t & 31, w = t >> 5;
    const int a0 = blockIdx.x * 112;
    const int b  = blockIdx.y;

    const float* qb = Q + (size_t)b * NA * DK;
    const float* kb = Kb + (size_t)b * DK * NB;

    float acc[2][14][4];
    #pragma unroll
    for (int mt = 0; mt < 2; mt++)
        #pragma unroll
        for (int j = 0; j < 14; j++)
            #pragma unroll
            for (int q = 0; q < 4; q++) acc[mt][j][q] = 0.f;

    #pragma unroll 1
    for (int kc = 0; kc < 8; kc++) {
        __syncthreads();
        // A = K^T: row n = t, cols k (32). Coalesced gmem reads along n.
        #pragma unroll
        for (int i = 0; i < 32; i++) {
            float v = (t < NB) ? kb[(size_t)(kc * 32 + i) * NB + t] : 0.f;
            unsigned short h, l;
            split2(v, h, l);
            *(unsigned short*)(smp + K1_AH + t * 80 + i * 2) = h;
            *(unsigned short*)(smp + K1_AL + t * 80 + i * 2) = l;
        }
        // B = Q rows (a-local 112) x 32 k
        #pragma unroll
        for (int i = 0; i < 16; i++) {
            int idx = t + i * 224;
            int r = idx >> 5, kk = idx & 31;
            int a = a0 + r;
            float v = (a < NA) ? qb[(size_t)a * DK + kc * 32 + kk] : 0.f;
            unsigned short h, l;
            split2(v, h, l);
            *(unsigned short*)(smp + K1_BH + r * 80 + kk * 2) = h;
            *(unsigned short*)(smp + K1_BL + r * 80 + kk * 2) = l;
        }
        __syncthreads();

        #pragma unroll
        for (int ks = 0; ks < 2; ks++) {
            u32 ah[2][4], al[2][4];
            #pragma unroll
            for (int mt = 0; mt < 2; mt++) {
                u32 arow = w * 32 + mt * 16 + (lane & 15);
                u32 acol = ks * 32 + ((lane >> 4) << 4);
                LDMX4(ah[mt], sb + K1_AH + arow * 80 + acol);
                LDMX4(al[mt], sb + K1_AL + arow * 80 + acol);
            }
            #pragma unroll
            for (int jj = 0; jj < 7; jj++) {
                u32 brow = jj * 16 + ((lane >> 4) << 3) + (lane & 7);
                u32 bcol = ks * 32 + (((lane >> 3) & 1) << 4);
                u32 bh[4], bl[4];
                LDMX4(bh, sb + K1_BH + brow * 80 + bcol);
                LDMX4(bl, sb + K1_BL + brow * 80 + bcol);
                #pragma unroll
                for (int mt = 0; mt < 2; mt++) {
                    #pragma unroll
                    for (int hf = 0; hf < 2; hf++) {
                        int j = jj * 2 + hf;
                        MMA16816(acc[mt][j], ah[mt], bh[hf * 2], bh[hf * 2 + 1]);
                        MMA16816(acc[mt][j], ah[mt], bl[hf * 2], bl[hf * 2 + 1]);
                        MMA16816(acc[mt][j], al[mt], bh[hf * 2], bh[hf * 2 + 1]);
                    }
                }
            }
        }
    }
    __syncthreads();   // staging dead; reuse as Csm [224 n][116 f32]

    float* Csm = (float*)smp;
    float* sinv = (float*)(smp + K1_SINV);
    const int g = lane >> 2, tq = lane & 3;
    #pragma unroll
    for (int mt = 0; mt < 2; mt++)
        #pragma unroll
        for (int j = 0; j < 14; j++) {
            int row = w * 32 + mt * 16 + g;
            int col = j * 8 + tq * 2;
            *(float2*)&Csm[row * 116 + col] = make_float2(acc[mt][j][0], acc[mt][j][1]);
            *(float2*)&Csm[(row + 8) * 116 + col] = make_float2(acc[mt][j][2], acc[mt][j][3]);
        }
    __syncthreads();

    // Warp-parallel column softmax: warp w -> a-cols [w*16, w*16+16).
    #pragma unroll 1
    for (int ci = 0; ci < 16; ci++) {
        int c = w * 16 + ci;
        float M = -1e30f;
        #pragma unroll
        for (int r = 0; r < 7; r++) {
            int n = lane + r * 32;
            if (n < NB) M = fmaxf(M, Csm[n * 116 + c]);
        }
        #pragma unroll
        for (int o = 16; o; o >>= 1)
            M = fmaxf(M, __shfl_xor_sync(0xFFFFFFFFu, M, o));
        float S = 0.f;
        #pragma unroll
        for (int r = 0; r < 7; r++) {
            int n = lane + r * 32;
            if (n < NB) {
                float e = __expf(SMOOTH_F * (Csm[n * 116 + c] - M));
                Csm[n * 116 + c] = e;
                S += e;
            }
        }
        #pragma unroll
        for (int o = 16; o; o >>= 1)
            S += __shfl_xor_sync(0xFFFFFFFFu, S, o);
        if (lane == 0)
            sinv[c] = (a0 + c < NA) ? (1.f / S) : 0.f;
    }
    __syncthreads();

    // Write pre-split planes (coalesced rows; zero rows for n >= 196).
    if (lane < 28) {
        float4 s4 = *(float4*)&sinv[lane * 4];
        for (int r = w; r < NP; r += 7) {
            uint2 hh = make_uint2(0u, 0u), ll = make_uint2(0u, 0u);
            if (r < NB) {
                float4 p = *(float4*)&Csm[r * 116 + lane * 4];
                p.x *= s4.x; p.y *= s4.y; p.z *= s4.z; p.w *= s4.w;
                unsigned short h[4], l[4];
                split2(p.x, h[0], l[0]); split2(p.y, h[1], l[1]);
                split2(p.z, h[2], l[2]); split2(p.w, h[3], l[3]);
                hh = make_uint2((u32)h[0] | ((u32)h[1] << 16), (u32)h[2] | ((u32)h[3] << 16));
                ll = make_uint2((u32)l[0] | ((u32)l[1] << 16), (u32)l[2] | ((u32)l[3] << 16));
            }
            size_t off = (size_t)(b * NP + r) * NP + a0 + lane * 4;
            *(uint2*)(g_ah + off) = hh;
            *(uint2*)(g_al + off) = ll;
        }
    }
}

// ============================================================================
// K2: out = gamma + V_a @ attn + V_b.
// Block: (m-tile 128 dims, batch). 256 threads = 8 warps (4 M x 2 N),
// warp tile m32 x n112 (round-7 shape). BOTH operands double-buffered per
// 32-k chunk so smem = 112.6 KB -> 2 CTAs/SM (the round-8 fix done right).
// ============================================================================
#define K2_ASTG 20480u                // per stage: 2 planes x (128 x 80B)
#define K2_B0   40960u                // B stages: [224 n][32 k] bf16, 80B stride
#define K2_BSTAGE 35840u              // per stage: 2 planes x 17920
#define K2_SMEM 112640u

__global__ void __launch_bounds__(256) xattn_k2(
    const float* __restrict__ VA,   // [B, DIM, NA]
    const float* __restrict__ VB,   // [B, DIM, NB]
    const float* __restrict__ G,
    float* __restrict__ O)          // [B, DIM, NB]
{
    extern __shared__ char smp[];
    const u32 sb = smem_u32(smp);
    const int t = threadIdx.x, lane = t & 31, w = t >> 5;
    const int wm = w >> 1, wn = w & 1;
    const int m0 = blockIdx.x * 128;
    const int b  = blockIdx.y;

    const float* va = VA + ((size_t)b * DIM + m0) * NA;
    const char* ghp = (const char*)g_ah;
    const char* glp = (const char*)g_al;

    // ---- prologue: B chunk 0 via cp.async, A chunk 0 split-stored to stage 0
    {
        #pragma unroll
        for (int i = 0; i < 7; i++) {
            int idx = t + i * 256;
            int p = idx / 896, rem = idx % 896;
            int n = rem >> 2, c = rem & 3;
            u32 dst = sb + K2_B0 + p * 17920 + n * 80 + c * 16;
            const char* base = p ? glp : ghp;
            const char* src = base + ((size_t)(b * NP + n) * NP + c * 8) * 2;
            CPASYNC16(dst, src);
        }
        CPCOMMIT();
        #pragma unroll
        for (int i = 0; i < 4; i++) {
            int idx = t + i * 256;
            int row = idx >> 3, q4 = idx & 7;
            int col = q4 * 4;
            float4 v = make_float4(0.f, 0.f, 0.f, 0.f);
            if (col < NA) v = *(const float4*)(va + (size_t)row * NA + col);
            unsigned short h[4], l[4];
            split2(v.x, h[0], l[0]); split2(v.y, h[1], l[1]);
            split2(v.z, h[2], l[2]); split2(v.w, h[3], l[3]);
            *(uint2*)(smp + row * 80 + col * 2) =
                make_uint2((u32)h[0] | ((u32)h[1] << 16), (u32)h[2] | ((u32)h[3] << 16));
            *(uint2*)(smp + 10240u + row * 80 + col * 2) =
                make_uint2((u32)l[0] | ((u32)l[1] << 16), (u32)l[2] | ((u32)l[3] << 16));
        }
    }

    float acc[2][14][4];
    #pragma unroll
    for (int mt = 0; mt < 2; mt++)
        #pragma unroll
        for (int j = 0; j < 14; j++)
            #pragma unroll
            for (int q = 0; q < 4; q++) acc[mt][j][q] = 0.f;

    #pragma unroll 1
    for (int kc = 0; kc < 7; kc++) {
        if (kc < 6) {   // prefetch next B chunk + fill next A stage
            const int nk = kc + 1, st = nk & 1;
            #pragma unroll
            for (int i = 0; i < 7; i++) {
                int idx = t + i * 256;
                int p = idx / 896, rem = idx % 896;
                int n = rem >> 2, c = rem & 3;
                u32 dst = sb + K2_B0 + st * K2_BSTAGE + p * 17920 + n * 80 + c * 16;
                const char* base = p ? glp : ghp;
                const char* src = base + ((size_t)(b * NP + n) * NP + nk * 32 + c * 8) * 2;
                CPASYNC16(dst, src);
            }
            #pragma unroll
            for (int i = 0; i < 4; i++) {
                int idx = t + i * 256;
                int row = idx >> 3, q4 = idx & 7;
                int col = q4 * 4;
                int ac = nk * 32 + col;
                float4 v = make_float4(0.f, 0.f, 0.f, 0.f);
                if (ac < NA) v = *(const float4*)(va + (size_t)row * NA + ac);
                unsigned short h[4], l[4];
                split2(v.x, h[0], l[0]); split2(v.y, h[1], l[1]);
                split2(v.z, h[2], l[2]); split2(v.w, h[3], l[3]);
                *(uint2*)(smp + st * K2_ASTG + row * 80 + col * 2) =
                    make_uint2((u32)h[0] | ((u32)h[1] << 16), (u32)h[2] | ((u32)h[3] << 16));
                *(uint2*)(smp + st * K2_ASTG + 10240u + row * 80 + col * 2) =
                    make_uint2((u32)l[0] | ((u32)l[1] << 16), (u32)l[2] | ((u32)l[3] << 16));
            }
        }
        CPCOMMIT();
        CPWAIT1();
        __syncthreads();

        const u32 ahb = sb + (kc & 1) * K2_ASTG;
        const u32 alb = ahb + 10240u;
        const u32 bhb = sb + K2_B0 + (kc & 1) * K2_BSTAGE;
        const u32 blb = bhb + 17920u;

        #pragma unroll
        for (int ks = 0; ks < 2; ks++) {
            u32 ah[2][4], al[2][4];
            #pragma unroll
            for (int mt = 0; mt < 2; mt++) {
                u32 arow = wm * 32 + mt * 16 + (lane & 15);
                u32 acol = ks * 32 + ((lane >> 4) << 4);
                LDMX4(ah[mt], ahb + arow * 80 + acol);
                LDMX4(al[mt], alb + arow * 80 + acol);
            }
            #pragma unroll
            for (int jj = 0; jj < 7; jj++) {
                u32 brow = wn * 112 + jj * 16 + ((lane >> 4) << 3) + (lane & 7);
                u32 bcol = ks * 32 + (((lane >> 3) & 1) << 4);
                u32 bh[4], bl[4];
                LDMX4(bh, bhb + brow * 80 + bcol);
                LDMX4(bl, blb + brow * 80 + bcol);
                #pragma unroll
                for (int mt = 0; mt < 2; mt++) {
                    #pragma unroll
                    for (int hf = 0; hf < 2; hf++) {
                        int j = jj * 2 + hf;
                        MMA16816(acc[mt][j], ah[mt], bh[hf * 2], bh[hf * 2 + 1]);
                        MMA16816(acc[mt][j], ah[mt], bl[hf * 2], bl[hf * 2 + 1]);
                        MMA16816(acc[mt][j], al[mt], bh[hf * 2], bh[hf * 2 + 1]);
                    }
                }
            }
        }
        __syncthreads();
    }

    // Epilogue: out = gamma + acc + V_b (guarded float2 stores)
    const float gam = G[0];
    const int g = lane >> 2, tq = lane & 3;
    #pragma unroll
    for (int mt = 0; mt < 2; mt++)
        #pragma unroll
        for (int j = 0; j < 14; j++) {
            int n = wn * 112 + j * 8 + tq * 2;
            if (n < NB) {
                int row = m0 + wm * 32 + mt * 16 + g;
                size_t o0 = ((size_t)(b * DIM + row)) * NB + n;
                size_t o1 = o0 + (size_t)8 * NB;
                float2 v0 = *(const float2*)(VB + o0);
                float2 v1 = *(const float2*)(VB + o1);
                *(float2*)(O + o0) = make_float2(gam + acc[mt][j][0] + v0.x,
                                                 gam + acc[mt][j][1] + v0.y);
                *(float2*)(O + o1) = make_float2(gam + acc[mt][j][2] + v1.x,
                                                 gam + acc[mt][j][3] + v1.y);
            }
        }
}

// ============================================================================
extern "C" void kernel_launch(void* const* d_in, const int* in_sizes, int n_in,
                              void* d_out, int out_size)
{
    const float* query_a = (const float*)d_in[0];
    const float* value_a = (const float*)d_in[1];
    const float* key_b   = (const float*)d_in[2];
    const float* value_b = (const float*)d_in[3];
    const float* gamma   = (const float*)d_in[4];
    float* out = (float*)d_out;

    cudaFuncSetAttribute(xattn_k1, cudaFuncAttributeMaxDynamicSharedMemorySize, K1_SMEM);
    cudaFuncSetAttribute(xattn_k2, cudaFuncAttributeMaxDynamicSharedMemorySize, K2_SMEM);

    xattn_k1<<<dim3(2, BATCH), 224, K1_SMEM>>>(query_a, key_b);
    xattn_k2<<<dim3(8, BATCH), 256, K2_SMEM>>>(value_a, value_b, gamma, out);
}

// round 10
// speedup vs baseline: 1.5181x; 1.1114x over previous
#include <cuda_runtime.h>
#include <cuda_bf16.h>
#include <cuda_fp16.h>
#include <cstdint>

#define BATCH 256
#define NA 196
#define NB 196
#define DK 256
#define DIM 1024
#define SMOOTH_F 4.0f
#define NP 224   // padded n / a dims

// Attention weights, transposed [b][n][a], single fp16 plane, zero-padded.
__device__ unsigned short g_ah[(size_t)BATCH * NP * NP];

typedef unsigned int u32;

__device__ __forceinline__ u32 smem_u32(const void* p) {
    u32 a;
    asm("{ .reg .u64 t; cvta.to.shared.u64 t, %1; cvt.u32.u64 %0, t; }" : "=r"(a) : "l"(p));
    return a;
}
// bf16 2-term split (k1 energy GEMM — softmax-sensitive, keep high precision)
__device__ __forceinline__ void split2(float x, unsigned short& h, unsigned short& l) {
    __nv_bfloat16 hb = __float2bfloat16_rn(x);
    float r = x - __bfloat162float(hb);
    h = __bfloat16_as_ushort(hb);
    l = __bfloat16_as_ushort(__float2bfloat16_rn(r));
}
// fp16 2-term split (k2 V_a — exact to ~2^-22)
__device__ __forceinline__ void split2h(float x, unsigned short& h, unsigned short& l) {
    __half hb = __float2half_rn(x);
    float r = x - __half2float(hb);
    h = __half_as_ushort(hb);
    l = __half_as_ushort(__float2half_rn(r));
}

#define LDMX4(r, a) asm volatile( \
    "ldmatrix.sync.aligned.m8n8.x4.shared.b16 {%0,%1,%2,%3}, [%4];" \
    : "=r"((r)[0]), "=r"((r)[1]), "=r"((r)[2]), "=r"((r)[3]) : "r"(a))

#define MMA16816(d, a, b0, b1) asm volatile( \
    "mma.sync.aligned.m16n8k16.row.col.f32.bf16.bf16.f32 " \
    "{%0,%1,%2,%3}, {%4,%5,%6,%7}, {%8,%9}, {%0,%1,%2,%3};" \
    : "+f"((d)[0]), "+f"((d)[1]), "+f"((d)[2]), "+f"((d)[3]) \
    : "r"((a)[0]), "r"((a)[1]), "r"((a)[2]), "r"((a)[3]), "r"(b0), "r"(b1))

#define MMAF16816(d, a, b0, b1) asm volatile( \
    "mma.sync.aligned.m16n8k16.row.col.f32.f16.f16.f32 " \
    "{%0,%1,%2,%3}, {%4,%5,%6,%7}, {%8,%9}, {%0,%1,%2,%3};" \
    : "+f"((d)[0]), "+f"((d)[1]), "+f"((d)[2]), "+f"((d)[3]) \
    : "r"((a)[0]), "r"((a)[1]), "r"((a)[2]), "r"((a)[3]), "r"(b0), "r"(b1))

#define CPASYNC16(dst, src) asm volatile( \
    "cp.async.cg.shared.global [%0], [%1], 16;" :: "r"(dst), "l"(src))
#define CPCOMMIT() asm volatile("cp.async.commit_group;")
#define CPWAIT1() asm volatile("cp.async.wait_group 1;")

// ============================================================================
// K1: energyT[n][a] = K_b^T @ Q_a^T (bf16 2-term split, 3 MMA products),
//     warp-parallel column softmax, write fp16 attn plane.
// Block: (a-half, batch). 224 threads = 7 warps; warp = 32 n-rows x 112 a-cols.
// ============================================================================
#define K1_AH 0u
#define K1_AL 17920u      // A planes: [224 n][32 k] bf16, 80B row stride
#define K1_BH 35840u      // B planes: [112 a][32 k] bf16, 80B row stride
#define K1_BL 44800u      // staging end = 53760; Csm overlay [224][116] f32
#define K1_SINV 103936u   // 112 floats
#define K1_SMEM 104384u

__global__ void __launch_bounds__(224) xattn_k1(
    const float* __restrict__ Q,    // [B, NA, DK]
    const float* __restrict__ Kb)   // [B, DK, NB]
{
    extern __shared__ char smp[];
    const u32 sb = smem_u32(smp);
    const int t = threadIdx.x, lane = t & 31, w = t >> 5;
    const int a0 = blockIdx.x * 112;
    const int b  = blockIdx.y;

    const float* qb = Q + (size_t)b * NA * DK;
    const float* kb = Kb + (size_t)b * DK * NB;

    float acc[2][14][4];
    #pragma unroll
    for (int mt = 0; mt < 2; mt++)
        #pragma unroll
        for (int j = 0; j < 14; j++)
            #pragma unroll
            for (int q = 0; q < 4; q++) acc[mt][j][q] = 0.f;

    #pragma unroll 1
    for (int kc = 0; kc < 8; kc++) {
        __syncthreads();
        // A = K^T: row n = t, cols k (32). Coalesced gmem reads along n.
        #pragma unroll
        for (int i = 0; i < 32; i++) {
            float v = (t < NB) ? kb[(size_t)(kc * 32 + i) * NB + t] : 0.f;
            unsigned short h, l;
            split2(v, h, l);
            *(unsigned short*)(smp + K1_AH + t * 80 + i * 2) = h;
            *(unsigned short*)(smp + K1_AL + t * 80 + i * 2) = l;
        }
        // B = Q rows (a-local 112) x 32 k
        #pragma unroll
        for (int i = 0; i < 16; i++) {
            int idx = t + i * 224;
            int r = idx >> 5, kk = idx & 31;
            int a = a0 + r;
            float v = (a < NA) ? qb[(size_t)a * DK + kc * 32 + kk] : 0.f;
            unsigned short h, l;
            split2(v, h, l);
            *(unsigned short*)(smp + K1_BH + r * 80 + kk * 2) = h;
            *(unsigned short*)(smp + K1_BL + r * 80 + kk * 2) = l;
        }
        __syncthreads();

        #pragma unroll
        for (int ks = 0; ks < 2; ks++) {
            u32 ah[2][4], al[2][4];
            #pragma unroll
            for (int mt = 0; mt < 2; mt++) {
                u32 arow = w * 32 + mt * 16 + (lane & 15);
                u32 acol = ks * 32 + ((lane >> 4) << 4);
                LDMX4(ah[mt], sb + K1_AH + arow * 80 + acol);
                LDMX4(al[mt], sb + K1_AL + arow * 80 + acol);
            }
            #pragma unroll
            for (int jj = 0; jj < 7; jj++) {
                u32 brow = jj * 16 + ((lane >> 4) << 3) + (lane & 7);
                u32 bcol = ks * 32 + (((lane >> 3) & 1) << 4);
                u32 bh[4], bl[4];
                LDMX4(bh, sb + K1_BH + brow * 80 + bcol);
                LDMX4(bl, sb + K1_BL + brow * 80 + bcol);
                #pragma unroll
                for (int mt = 0; mt < 2; mt++) {
                    #pragma unroll
                    for (int hf = 0; hf < 2; hf++) {
                        int j = jj * 2 + hf;
                        MMA16816(acc[mt][j], ah[mt], bh[hf * 2], bh[hf * 2 + 1]);
                        MMA16816(acc[mt][j], ah[mt], bl[hf * 2], bl[hf * 2 + 1]);
                        MMA16816(acc[mt][j], al[mt], bh[hf * 2], bh[hf * 2 + 1]);
                    }
                }
            }
        }
    }
    __syncthreads();   // staging dead; reuse as Csm [224 n][116 f32]

    float* Csm = (float*)smp;
    float* sinv = (float*)(smp + K1_SINV);
    const int g = lane >> 2, tq = lane & 3;
    #pragma unroll
    for (int mt = 0; mt < 2; mt++)
        #pragma unroll
        for (int j = 0; j < 14; j++) {
            int row = w * 32 + mt * 16 + g;
            int col = j * 8 + tq * 2;
            *(float2*)&Csm[row * 116 + col] = make_float2(acc[mt][j][0], acc[mt][j][1]);
            *(float2*)&Csm[(row + 8) * 116 + col] = make_float2(acc[mt][j][2], acc[mt][j][3]);
        }
    __syncthreads();

    // Warp-parallel column softmax: warp w -> a-cols [w*16, w*16+16).
    #pragma unroll 1
    for (int ci = 0; ci < 16; ci++) {
        int c = w * 16 + ci;
        float M = -1e30f;
        #pragma unroll
        for (int r = 0; r < 7; r++) {
            int n = lane + r * 32;
            if (n < NB) M = fmaxf(M, Csm[n * 116 + c]);
        }
        #pragma unroll
        for (int o = 16; o; o >>= 1)
            M = fmaxf(M, __shfl_xor_sync(0xFFFFFFFFu, M, o));
        float S = 0.f;
        #pragma unroll
        for (int r = 0; r < 7; r++) {
            int n = lane + r * 32;
            if (n < NB) {
                float e = __expf(SMOOTH_F * (Csm[n * 116 + c] - M));
                Csm[n * 116 + c] = e;
                S += e;
            }
        }
        #pragma unroll
        for (int o = 16; o; o >>= 1)
            S += __shfl_xor_sync(0xFFFFFFFFu, S, o);
        if (lane == 0)
            sinv[c] = (a0 + c < NA) ? (1.f / S) : 0.f;
    }
    __syncthreads();

    // Write fp16 attn plane (coalesced rows; zero rows for n >= 196).
    if (lane < 28) {
        float4 s4 = *(float4*)&sinv[lane * 4];
        for (int r = w; r < NP; r += 7) {
            uint2 hh = make_uint2(0u, 0u);
            if (r < NB) {
                float4 p = *(float4*)&Csm[r * 116 + lane * 4];
                unsigned short h0 = __half_as_ushort(__float2half_rn(p.x * s4.x));
                unsigned short h1 = __half_as_ushort(__float2half_rn(p.y * s4.y));
                unsigned short h2 = __half_as_ushort(__float2half_rn(p.z * s4.z));
                unsigned short h3 = __half_as_ushort(__float2half_rn(p.w * s4.w));
                hh = make_uint2((u32)h0 | ((u32)h1 << 16), (u32)h2 | ((u32)h3 << 16));
            }
            size_t off = (size_t)(b * NP + r) * NP + a0 + lane * 4;
            *(uint2*)(g_ah + off) = hh;
        }
    }
}

// ============================================================================
// K2: out = gamma + V_a @ attn + V_b  (fp16: V_a 2-plane split x attn 1 plane
// = 2 MMA products; was 3 bf16 products with 2 B planes).
// Block: (m-tile 128 dims, batch). 256 threads = 8 warps (4 M x 2 N),
// warp tile m32 x n112. Both operands double-buffered per 32-k chunk.
// ============================================================================
#define K2_ASTG 20480u                // per stage: 2 planes x (128 x 80B)
#define K2_B0   40960u                // B stages: [224 n][32 k] fp16, 80B stride
#define K2_BSTAGE 17920u              // single plane per stage
#define K2_SMEM 76800u

__global__ void __launch_bounds__(256) xattn_k2(
    const float* __restrict__ VA,   // [B, DIM, NA]
    const float* __restrict__ VB,   // [B, DIM, NB]
    const float* __restrict__ G,
    float* __restrict__ O)          // [B, DIM, NB]
{
    extern __shared__ char smp[];
    const u32 sb = smem_u32(smp);
    const int t = threadIdx.x, lane = t & 31, w = t >> 5;
    const int wm = w >> 1, wn = w & 1;
    const int m0 = blockIdx.x * 128;
    const int b  = blockIdx.y;

    const float* va = VA + ((size_t)b * DIM + m0) * NA;
    const char* ghp = (const char*)g_ah;

    // ---- prologue: B chunk 0 via cp.async, A chunk 0 split-stored to stage 0
    {
        #pragma unroll
        for (int i = 0; i < 4; i++) {
            int idx = t + i * 256;
            if (idx < 896) {
                int n = idx >> 2, c = idx & 3;
                u32 dst = sb + K2_B0 + n * 80 + c * 16;
                const char* src = ghp + ((size_t)(b * NP + n) * NP + c * 8) * 2;
                CPASYNC16(dst, src);
            }
        }
        CPCOMMIT();
        #pragma unroll
        for (int i = 0; i < 4; i++) {
            int idx = t + i * 256;
            int row = idx >> 3, q4 = idx & 7;
            int col = q4 * 4;
            float4 v = make_float4(0.f, 0.f, 0.f, 0.f);
            if (col < NA) v = *(const float4*)(va + (size_t)row * NA + col);
            unsigned short h[4], l[4];
            split2h(v.x, h[0], l[0]); split2h(v.y, h[1], l[1]);
            split2h(v.z, h[2], l[2]); split2h(v.w, h[3], l[3]);
            *(uint2*)(smp + row * 80 + col * 2) =
                make_uint2((u32)h[0] | ((u32)h[1] << 16), (u32)h[2] | ((u32)h[3] << 16));
            *(uint2*)(smp + 10240u + row * 80 + col * 2) =
                make_uint2((u32)l[0] | ((u32)l[1] << 16), (u32)l[2] | ((u32)l[3] << 16));
        }
    }

    float acc[2][14][4];
    #pragma unroll
    for (int mt = 0; mt < 2; mt++)
        #pragma unroll
        for (int j = 0; j < 14; j++)
            #pragma unroll
            for (int q = 0; q < 4; q++) acc[mt][j][q] = 0.f;

    #pragma unroll 1
    for (int kc = 0; kc < 7; kc++) {
        if (kc < 6) {   // prefetch next B chunk + fill next A stage
            const int nk = kc + 1, st = nk & 1;
            #pragma unroll
            for (int i = 0; i < 4; i++) {
                int idx = t + i * 256;
                if (idx < 896) {
                    int n = idx >> 2, c = idx & 3;
                    u32 dst = sb + K2_B0 + st * K2_BSTAGE + n * 80 + c * 16;
                    const char* src = ghp + ((size_t)(b * NP + n) * NP + nk * 32 + c * 8) * 2;
                    CPASYNC16(dst, src);
                }
            }
            #pragma unroll
            for (int i = 0; i < 4; i++) {
                int idx = t + i * 256;
                int row = idx >> 3, q4 = idx & 7;
                int col = q4 * 4;
                int ac = nk * 32 + col;
                float4 v = make_float4(0.f, 0.f, 0.f, 0.f);
                if (ac < NA) v = *(const float4*)(va + (size_t)row * NA + ac);
                unsigned short h[4], l[4];
                split2h(v.x, h[0], l[0]); split2h(v.y, h[1], l[1]);
                split2h(v.z, h[2], l[2]); split2h(v.w, h[3], l[3]);
                *(uint2*)(smp + st * K2_ASTG + row * 80 + col * 2) =
                    make_uint2((u32)h[0] | ((u32)h[1] << 16), (u32)h[2] | ((u32)h[3] << 16));
                *(uint2*)(smp + st * K2_ASTG + 10240u + row * 80 + col * 2) =
                    make_uint2((u32)l[0] | ((u32)l[1] << 16), (u32)l[2] | ((u32)l[3] << 16));
            }
        }
        CPCOMMIT();
        CPWAIT1();
        __syncthreads();

        const u32 ahb = sb + (kc & 1) * K2_ASTG;
        const u32 alb = ahb + 10240u;
        const u32 bhb = sb + K2_B0 + (kc & 1) * K2_BSTAGE;

        #pragma unroll
        for (int ks = 0; ks < 2; ks++) {
            u32 ah[2][4], al[2][4];
            #pragma unroll
            for (int mt = 0; mt < 2; mt++) {
                u32 arow = wm * 32 + mt * 16 + (lane & 15);
                u32 acol = ks * 32 + ((lane >> 4) << 4);
                LDMX4(ah[mt], ahb + arow * 80 + acol);
                LDMX4(al[mt], alb + arow * 80 + acol);
            }
            #pragma unroll
            for (int jj = 0; jj < 7; jj++) {
                u32 brow = wn * 112 + jj * 16 + ((lane >> 4) << 3) + (lane & 7);
                u32 bcol = ks * 32 + (((lane >> 3) & 1) << 4);
                u32 bh[4];
                LDMX4(bh, bhb + brow * 80 + bcol);
                #pragma unroll
                for (int mt = 0; mt < 2; mt++) {
                    #pragma unroll
                    for (int hf = 0; hf < 2; hf++) {
                        int j = jj * 2 + hf;
                        MMAF16816(acc[mt][j], ah[mt], bh[hf * 2], bh[hf * 2 + 1]);
                        MMAF16816(acc[mt][j], al[mt], bh[hf * 2], bh[hf * 2 + 1]);
                    }
                }
            }
        }
        __syncthreads();
    }

    // Epilogue: out = gamma + acc + V_b (guarded float2 stores)
    const float gam = G[0];
    const int g = lane >> 2, tq = lane & 3;
    #pragma unroll
    for (int mt = 0; mt < 2; mt++)
        #pragma unroll
        for (int j = 0; j < 14; j++) {
            int n = wn * 112 + j * 8 + tq * 2;
            if (n < NB) {
                int row = m0 + wm * 32 + mt * 16 + g;
                size_t o0 = ((size_t)(b * DIM + row)) * NB + n;
                size_t o1 = o0 + (size_t)8 * NB;
                float2 v0 = *(const float2*)(VB + o0);
                float2 v1 = *(const float2*)(VB + o1);
                *(float2*)(O + o0) = make_float2(gam + acc[mt][j][0] + v0.x,
                                                 gam + acc[mt][j][1] + v0.y);
                *(float2*)(O + o1) = make_float2(gam + acc[mt][j][2] + v1.x,
                                                 gam + acc[mt][j][3] + v1.y);
            }
        }
}

// ============================================================================
extern "C" void kernel_launch(void* const* d_in, const int* in_sizes, int n_in,
                              void* d_out, int out_size)
{
    const float* query_a = (const float*)d_in[0];
    const float* value_a = (const float*)d_in[1];
    const float* key_b   = (const float*)d_in[2];
    const float* value_b = (const float*)d_in[3];
    const float* gamma   = (const float*)d_in[4];
    float* out = (float*)d_out;

    cudaFuncSetAttribute(xattn_k1, cudaFuncAttributeMaxDynamicSharedMemorySize, K1_SMEM);
    cudaFuncSetAttribute(xattn_k2, cudaFuncAttributeMaxDynamicSharedMemorySize, K2_SMEM);

    xattn_k1<<<dim3(2, BATCH), 224, K1_SMEM>>>(query_a, key_b);
    xattn_k2<<<dim3(8, BATCH), 256, K2_SMEM>>>(value_a, value_b, gamma, out);
}

// round 11
// speedup vs baseline: 1.6853x; 1.1101x over previous
#include <cuda_runtime.h>
#include <cuda_bf16.h>
#include <cuda_fp16.h>
#include <cstdint>

#define BATCH 256
#define NA 196
#define NB 196
#define DK 256
#define DIM 1024
#define SMOOTH_F 4.0f
#define NP 224   // padded n / a dims

// Attention weights, transposed [b][n][a], single fp16 plane, zero-padded.
__device__ unsigned short g_ah[(size_t)BATCH * NP * NP];

typedef unsigned int u32;

__device__ __forceinline__ u32 smem_u32(const void* p) {
    u32 a;
    asm("{ .reg .u64 t; cvta.to.shared.u64 t, %1; cvt.u32.u64 %0, t; }" : "=r"(a) : "l"(p));
    return a;
}
// bf16 2-term split (k1 energy GEMM — softmax-sensitive, keep high precision)
__device__ __forceinline__ void split2(float x, unsigned short& h, unsigned short& l) {
    __nv_bfloat16 hb = __float2bfloat16_rn(x);
    float r = x - __bfloat162float(hb);
    h = __bfloat16_as_ushort(hb);
    l = __bfloat16_as_ushort(__float2bfloat16_rn(r));
}
// fp16 2-term split (k2 V_a — exact to ~2^-22)
__device__ __forceinline__ void split2h(float x, unsigned short& h, unsigned short& l) {
    __half hb = __float2half_rn(x);
    float r = x - __half2float(hb);
    h = __half_as_ushort(hb);
    l = __half_as_ushort(__float2half_rn(r));
}

#define LDMX4(r, a) asm volatile( \
    "ldmatrix.sync.aligned.m8n8.x4.shared.b16 {%0,%1,%2,%3}, [%4];" \
    : "=r"((r)[0]), "=r"((r)[1]), "=r"((r)[2]), "=r"((r)[3]) : "r"(a))

#define MMA16816(d, a, b0, b1) asm volatile( \
    "mma.sync.aligned.m16n8k16.row.col.f32.bf16.bf16.f32 " \
    "{%0,%1,%2,%3}, {%4,%5,%6,%7}, {%8,%9}, {%0,%1,%2,%3};" \
    : "+f"((d)[0]), "+f"((d)[1]), "+f"((d)[2]), "+f"((d)[3]) \
    : "r"((a)[0]), "r"((a)[1]), "r"((a)[2]), "r"((a)[3]), "r"(b0), "r"(b1))

#define MMAF16816(d, a, b0, b1) asm volatile( \
    "mma.sync.aligned.m16n8k16.row.col.f32.f16.f16.f32 " \
    "{%0,%1,%2,%3}, {%4,%5,%6,%7}, {%8,%9}, {%0,%1,%2,%3};" \
    : "+f"((d)[0]), "+f"((d)[1]), "+f"((d)[2]), "+f"((d)[3]) \
    : "r"((a)[0]), "r"((a)[1]), "r"((a)[2]), "r"((a)[3]), "r"(b0), "r"(b1))

#define CPASYNC16(dst, src) asm volatile( \
    "cp.async.cg.shared.global [%0], [%1], 16;" :: "r"(dst), "l"(src))
#define CPCOMMIT() asm volatile("cp.async.commit_group;")
#define CPWAIT1() asm volatile("cp.async.wait_group 1;")

// ============================================================================
// K1: energyT[n][a] = K_b^T @ Q_a^T (bf16 2-term split, 3 MMA products),
//     warp-parallel column softmax, write fp16 attn plane.
// Block: (a-half, batch). 224 threads = 7 warps; warp = 32 n-rows x 112 a-cols.
// ============================================================================
#define K1_AH 0u
#define K1_AL 17920u      // A planes: [224 n][32 k] bf16, 80B row stride
#define K1_BH 35840u      // B planes: [112 a][32 k] bf16, 80B row stride
#define K1_BL 44800u      // staging end = 53760; Csm overlay [224][116] f32
#define K1_SINV 103936u   // 112 floats
#define K1_SMEM 104384u

__global__ void __launch_bounds__(224) xattn_k1(
    const float* __restrict__ Q,    // [B, NA, DK]
    const float* __restrict__ Kb)   // [B, DK, NB]
{
    extern __shared__ char smp[];
    const u32 sb = smem_u32(smp);
    const int t = threadIdx.x, lane = t & 31, w = t >> 5;
    const int a0 = blockIdx.x * 112;
    const int b  = blockIdx.y;

    const float* qb = Q + (size_t)b * NA * DK;
    const float* kb = Kb + (size_t)b * DK * NB;

    float acc[2][14][4];
    #pragma unroll
    for (int mt = 0; mt < 2; mt++)
        #pragma unroll
        for (int j = 0; j < 14; j++)
            #pragma unroll
            for (int q = 0; q < 4; q++) acc[mt][j][q] = 0.f;

    #pragma unroll 1
    for (int kc = 0; kc < 8; kc++) {
        __syncthreads();
        // A = K^T: row n = t, cols k (32). Coalesced gmem reads along n.
        #pragma unroll
        for (int i = 0; i < 32; i++) {
            float v = (t < NB) ? kb[(size_t)(kc * 32 + i) * NB + t] : 0.f;
            unsigned short h, l;
            split2(v, h, l);
            *(unsigned short*)(smp + K1_AH + t * 80 + i * 2) = h;
            *(unsigned short*)(smp + K1_AL + t * 80 + i * 2) = l;
        }
        // B = Q rows (a-local 112) x 32 k
        #pragma unroll
        for (int i = 0; i < 16; i++) {
            int idx = t + i * 224;
            int r = idx >> 5, kk = idx & 31;
            int a = a0 + r;
            float v = (a < NA) ? qb[(size_t)a * DK + kc * 32 + kk] : 0.f;
            unsigned short h, l;
            split2(v, h, l);
            *(unsigned short*)(smp + K1_BH + r * 80 + kk * 2) = h;
            *(unsigned short*)(smp + K1_BL + r * 80 + kk * 2) = l;
        }
        __syncthreads();

        #pragma unroll
        for (int ks = 0; ks < 2; ks++) {
            u32 ah[2][4], al[2][4];
            #pragma unroll
            for (int mt = 0; mt < 2; mt++) {
                u32 arow = w * 32 + mt * 16 + (lane & 15);
                u32 acol = ks * 32 + ((lane >> 4) << 4);
                LDMX4(ah[mt], sb + K1_AH + arow * 80 + acol);
                LDMX4(al[mt], sb + K1_AL + arow * 80 + acol);
            }
            #pragma unroll
            for (int jj = 0; jj < 7; jj++) {
                u32 brow = jj * 16 + ((lane >> 4) << 3) + (lane & 7);
                u32 bcol = ks * 32 + (((lane >> 3) & 1) << 4);
                u32 bh[4], bl[4];
                LDMX4(bh, sb + K1_BH + brow * 80 + bcol);
                LDMX4(bl, sb + K1_BL + brow * 80 + bcol);
                #pragma unroll
                for (int mt = 0; mt < 2; mt++) {
                    #pragma unroll
                    for (int hf = 0; hf < 2; hf++) {
                        int j = jj * 2 + hf;
                        MMA16816(acc[mt][j], ah[mt], bh[hf * 2], bh[hf * 2 + 1]);
                        MMA16816(acc[mt][j], ah[mt], bl[hf * 2], bl[hf * 2 + 1]);
                        MMA16816(acc[mt][j], al[mt], bh[hf * 2], bh[hf * 2 + 1]);
                    }
                }
            }
        }
    }
    __syncthreads();   // staging dead; reuse as Csm [224 n][116 f32]

    float* Csm = (float*)smp;
    float* sinv = (float*)(smp + K1_SINV);
    const int g = lane >> 2, tq = lane & 3;
    #pragma unroll
    for (int mt = 0; mt < 2; mt++)
        #pragma unroll
        for (int j = 0; j < 14; j++) {
            int row = w * 32 + mt * 16 + g;
            int col = j * 8 + tq * 2;
            *(float2*)&Csm[row * 116 + col] = make_float2(acc[mt][j][0], acc[mt][j][1]);
            *(float2*)&Csm[(row + 8) * 116 + col] = make_float2(acc[mt][j][2], acc[mt][j][3]);
        }
    __syncthreads();

    // Warp-parallel column softmax: warp w -> a-cols [w*16, w*16+16).
    #pragma unroll 1
    for (int ci = 0; ci < 16; ci++) {
        int c = w * 16 + ci;
        float M = -1e30f;
        #pragma unroll
        for (int r = 0; r < 7; r++) {
            int n = lane + r * 32;
            if (n < NB) M = fmaxf(M, Csm[n * 116 + c]);
        }
        #pragma unroll
        for (int o = 16; o; o >>= 1)
            M = fmaxf(M, __shfl_xor_sync(0xFFFFFFFFu, M, o));
        float S = 0.f;
        #pragma unroll
        for (int r = 0; r < 7; r++) {
            int n = lane + r * 32;
            if (n < NB) {
                float e = __expf(SMOOTH_F * (Csm[n * 116 + c] - M));
                Csm[n * 116 + c] = e;
                S += e;
            }
        }
        #pragma unroll
        for (int o = 16; o; o >>= 1)
            S += __shfl_xor_sync(0xFFFFFFFFu, S, o);
        if (lane == 0)
            sinv[c] = (a0 + c < NA) ? (1.f / S) : 0.f;
    }
    __syncthreads();

    // Write fp16 attn plane (coalesced rows; zero rows for n >= 196).
    if (lane < 28) {
        float4 s4 = *(float4*)&sinv[lane * 4];
        for (int r = w; r < NP; r += 7) {
            uint2 hh = make_uint2(0u, 0u);
            if (r < NB) {
                float4 p = *(float4*)&Csm[r * 116 + lane * 4];
                unsigned short h0 = __half_as_ushort(__float2half_rn(p.x * s4.x));
                unsigned short h1 = __half_as_ushort(__float2half_rn(p.y * s4.y));
                unsigned short h2 = __half_as_ushort(__float2half_rn(p.z * s4.z));
                unsigned short h3 = __half_as_ushort(__float2half_rn(p.w * s4.w));
                hh = make_uint2((u32)h0 | ((u32)h1 << 16), (u32)h2 | ((u32)h3 << 16));
            }
            size_t off = (size_t)(b * NP + r) * NP + a0 + lane * 4;
            *(uint2*)(g_ah + off) = hh;
        }
    }
}

// ============================================================================
// K2: out = gamma + V_a @ attn + V_b  (fp16: V_a 2-plane split x attn 1 plane).
// Block: 128 threads = 4 M-warps, tile m128 x n112 (n split across blocks).
// Warp tile UNCHANGED m32 x n112 -> same LDSM:MMA ratio, but 3 CTAs/SM
// (21.5K regs + 57.5KB smem per CTA) = 12 warps/SM for latency hiding.
// ============================================================================
#define K2_ASTG 20480u                // per stage: 2 planes x (128 x 80B)
#define K2_B0   40960u                // B stages: [112 n][32 k] fp16, 80B stride
#define K2_BSTAGE 8960u               // single plane per stage
#define K2_SMEM 58880u

__global__ void __launch_bounds__(128, 3) xattn_k2(
    const float* __restrict__ VA,   // [B, DIM, NA]
    const float* __restrict__ VB,   // [B, DIM, NB]
    const float* __restrict__ G,
    float* __restrict__ O)          // [B, DIM, NB]
{
    extern __shared__ char smp[];
    const u32 sb = smem_u32(smp);
    const int t = threadIdx.x, lane = t & 31, w = t >> 5;
    const int m0  = (blockIdx.x >> 1) * 128;
    const int nb0 = (blockIdx.x & 1) * 112;
    const int b   = blockIdx.y;

    const float* va = VA + ((size_t)b * DIM + m0) * NA;
    const char* ghp = (const char*)g_ah;

    // ---- prologue: B chunk 0 via cp.async, A chunk 0 split-stored to stage 0
    {
        #pragma unroll
        for (int i = 0; i < 4; i++) {
            int idx = t + i * 128;
            if (idx < 448) {
                int n = idx >> 2, c = idx & 3;
                u32 dst = sb + K2_B0 + n * 80 + c * 16;
                const char* src = ghp + ((size_t)(b * NP + nb0 + n) * NP + c * 8) * 2;
                CPASYNC16(dst, src);
            }
        }
        CPCOMMIT();
        #pragma unroll
        for (int i = 0; i < 8; i++) {
            int idx = t + i * 128;
            int row = idx >> 3, q4 = idx & 7;
            int col = q4 * 4;
            float4 v = make_float4(0.f, 0.f, 0.f, 0.f);
            if (col < NA) v = *(const float4*)(va + (size_t)row * NA + col);
            unsigned short h[4], l[4];
            split2h(v.x, h[0], l[0]); split2h(v.y, h[1], l[1]);
            split2h(v.z, h[2], l[2]); split2h(v.w, h[3], l[3]);
            *(uint2*)(smp + row * 80 + col * 2) =
                make_uint2((u32)h[0] | ((u32)h[1] << 16), (u32)h[2] | ((u32)h[3] << 16));
            *(uint2*)(smp + 10240u + row * 80 + col * 2) =
                make_uint2((u32)l[0] | ((u32)l[1] << 16), (u32)l[2] | ((u32)l[3] << 16));
        }
    }

    float acc[2][14][4];
    #pragma unroll
    for (int mt = 0; mt < 2; mt++)
        #pragma unroll
        for (int j = 0; j < 14; j++)
            #pragma unroll
            for (int q = 0; q < 4; q++) acc[mt][j][q] = 0.f;

    #pragma unroll 1
    for (int kc = 0; kc < 7; kc++) {
        if (kc < 6) {   // prefetch next B chunk + fill next A stage
            const int nk = kc + 1, st = nk & 1;
            #pragma unroll
            for (int i = 0; i < 4; i++) {
                int idx = t + i * 128;
                if (idx < 448) {
                    int n = idx >> 2, c = idx & 3;
                    u32 dst = sb + K2_B0 + st * K2_BSTAGE + n * 80 + c * 16;
                    const char* src = ghp +
                        ((size_t)(b * NP + nb0 + n) * NP + nk * 32 + c * 8) * 2;
                    CPASYNC16(dst, src);
                }
            }
            #pragma unroll
            for (int i = 0; i < 8; i++) {
                int idx = t + i * 128;
                int row = idx >> 3, q4 = idx & 7;
                int col = q4 * 4;
                int ac = nk * 32 + col;
                float4 v = make_float4(0.f, 0.f, 0.f, 0.f);
                if (ac < NA) v = *(const float4*)(va + (size_t)row * NA + ac);
                unsigned short h[4], l[4];
                split2h(v.x, h[0], l[0]); split2h(v.y, h[1], l[1]);
                split2h(v.z, h[2], l[2]); split2h(v.w, h[3], l[3]);
                *(uint2*)(smp + st * K2_ASTG + row * 80 + col * 2) =
                    make_uint2((u32)h[0] | ((u32)h[1] << 16), (u32)h[2] | ((u32)h[3] << 16));
                *(uint2*)(smp + st * K2_ASTG + 10240u + row * 80 + col * 2) =
                    make_uint2((u32)l[0] | ((u32)l[1] << 16), (u32)l[2] | ((u32)l[3] << 16));
            }
        }
        CPCOMMIT();
        CPWAIT1();
        __syncthreads();

        const u32 ahb = sb + (kc & 1) * K2_ASTG;
        const u32 alb = ahb + 10240u;
        const u32 bhb = sb + K2_B0 + (kc & 1) * K2_BSTAGE;

        #pragma unroll
        for (int ks = 0; ks < 2; ks++) {
            u32 ah[2][4], al[2][4];
            #pragma unroll
            for (int mt = 0; mt < 2; mt++) {
                u32 arow = w * 32 + mt * 16 + (lane & 15);
                u32 acol = ks * 32 + ((lane >> 4) << 4);
                LDMX4(ah[mt], ahb + arow * 80 + acol);
                LDMX4(al[mt], alb + arow * 80 + acol);
            }
            #pragma unroll
            for (int jj = 0; jj < 7; jj++) {
                u32 brow = jj * 16 + ((lane >> 4) << 3) + (lane & 7);
                u32 bcol = ks * 32 + (((lane >> 3) & 1) << 4);
                u32 bh[4];
                LDMX4(bh, bhb + brow * 80 + bcol);
                #pragma unroll
                for (int mt = 0; mt < 2; mt++) {
                    #pragma unroll
                    for (int hf = 0; hf < 2; hf++) {
                        int j = jj * 2 + hf;
                        MMAF16816(acc[mt][j], ah[mt], bh[hf * 2], bh[hf * 2 + 1]);
                        MMAF16816(acc[mt][j], al[mt], bh[hf * 2], bh[hf * 2 + 1]);
                    }
                }
            }
        }
        __syncthreads();
    }

    // Epilogue: out = gamma + acc + V_b (guarded float2 stores)
    const float gam = G[0];
    const int g = lane >> 2, tq = lane & 3;
    #pragma unroll
    for (int mt = 0; mt < 2; mt++)
        #pragma unroll
        for (int j = 0; j < 14; j++) {
            int n = nb0 + j * 8 + tq * 2;
            if (n < NB) {
                int row = m0 + w * 32 + mt * 16 + g;
                size_t o0 = ((size_t)(b * DIM + row)) * NB + n;
                size_t o1 = o0 + (size_t)8 * NB;
                float2 v0 = *(const float2*)(VB + o0);
                float2 v1 = *(const float2*)(VB + o1);
                *(float2*)(O + o0) = make_float2(gam + acc[mt][j][0] + v0.x,
                                                 gam + acc[mt][j][1] + v0.y);
                *(float2*)(O + o1) = make_float2(gam + acc[mt][j][2] + v1.x,
                                                 gam + acc[mt][j][3] + v1.y);
            }
        }
}

// ============================================================================
extern "C" void kernel_launch(void* const* d_in, const int* in_sizes, int n_in,
                              void* d_out, int out_size)
{
    const float* query_a = (const float*)d_in[0];
    const float* value_a = (const float*)d_in[1];
    const float* key_b   = (const float*)d_in[2];
    const float* value_b = (const float*)d_in[3];
    const float* gamma   = (const float*)d_in[4];
    float* out = (float*)d_out;

    cudaFuncSetAttribute(xattn_k1, cudaFuncAttributeMaxDynamicSharedMemorySize, K1_SMEM);
    cudaFuncSetAttribute(xattn_k2, cudaFuncAttributeMaxDynamicSharedMemorySize, K2_SMEM);

    xattn_k1<<<dim3(2, BATCH), 224, K1_SMEM>>>(query_a, key_b);
    xattn_k2<<<dim3(16, BATCH), 128, K2_SMEM>>>(value_a, value_b, gamma, out);
}